// round 15
// baseline (speedup 1.0000x reference)
#include <cuda_runtime.h>
#include <cuda_bf16.h>

#define BATCH 128
#define DIM 128
#define K1 4097                              // K + 1
#define OUTPUT_SIZE 200000
#define NENTRIES (BATCH * K1)                // 524416 (b,k) pairs
#define SCORE_STRIDE NENTRIES                // per score plane
#define BANK_ELEMS (OUTPUT_SIZE * DIM)       // 25,600,000 floats per bank
#define MOMENTUM 0.5f

// Fixed-slot inverted index. Entries per row ~ Poisson(2.62); P(count>16)
// summed over 200000 rows ~ 2e-4 for a uniform draw; observed max 13 here.
#define SLOTS 16

// __device__ globals are zero-initialized at module load; g_cnt is re-zeroed
// by final_kernel every call, so "g_cnt == 0 on entry" holds for every call.
__device__ int      g_cnt[OUTPUT_SIZE];              // per-row entry count
__device__ unsigned g_entries[OUTPUT_SIZE * SLOTS];  // packed (b<<20)|i
__device__ float    g_scores[NENTRIES * 8];          // 6 sums, 32B/entry slot

// final_kernel geometry: 2 entries per thread (512 per block)
#define FBLKS ((NENTRIES + 511) / 512)               // 1025 transpose blocks
#define ZBLKS ((OUTPUT_SIZE / 4 + 255) / 256)        // 196 re-zero blocks

// ---------------------------------------------------------------------------
// 1) bucket every entry under its bank row (atomic bump allocation).
//    One entry per thread — max TLP (ILP variants regressed in R11/R12).
//    Bucket word packs b (7 bits) and entry id i (20 bits): no div in main.
// ---------------------------------------------------------------------------
__global__ void scatter_kernel(const int* __restrict__ idx) {
    const int i = blockIdx.x * blockDim.x + threadIdx.x;
    if (i >= NENTRIES) return;
    const int r = __ldcs(&idx[i]);
    const int pos = atomicAdd(&g_cnt[r], 1);
    const unsigned b = (unsigned)i / K1;             // one div here, not in main
    if (pos < SLOTS)
        g_entries[r * SLOTS + pos] = (b << 20) | (unsigned)i;
}

// ---------------------------------------------------------------------------
// 2) main sweep: one warp per bank row (R10/R13 configuration — empirically
//    the best shape; the kernel runs at the LTS throughput floor).
//    - 3 streaming float4 row reads (row lives in registers)
//    - 3 streaming stores = the bank copy
//    - bucket line prefetched to L1 while row loads are in flight
//    - per referencing entry: 3 L1-hot feature loads, 6 dots, 20-SHFL
//      two-phase reduction, one 32B-sector staging write.
// ---------------------------------------------------------------------------
__global__ __launch_bounds__(256) void main_kernel(
    const float* __restrict__ l,
    const float* __restrict__ ab,
    const float* __restrict__ ori,
    const float* __restrict__ ml,
    const float* __restrict__ mab,
    const float* __restrict__ mori,
    float* __restrict__ nl,
    float* __restrict__ nab,
    float* __restrict__ nori)
{
    const int warp = threadIdx.x >> 5;
    const int lane = threadIdx.x & 31;
    const int row  = blockIdx.x * 8 + warp;          // 25000*8 = 200000 exact

    const unsigned* __restrict__ bucket = g_entries + row * SLOTS;
    // warm the bucket line (written by scatter -> L2) into L1 while the
    // streaming row loads below are outstanding
    asm volatile("prefetch.global.L1 [%0];" :: "l"(bucket));

    const size_t voff = (size_t)row * 32 + lane;

    const float4 vl = __ldcs((const float4*)ml   + voff);
    const float4 va = __ldcs((const float4*)mab  + voff);
    const float4 vo = __ldcs((const float4*)mori + voff);

    __stcs((float4*)nl   + voff, vl);
    __stcs((float4*)nab  + voff, va);
    __stcs((float4*)nori + voff, vo);

    const int cnt = g_cnt[row];                      // warp-uniform broadcast
    const int v = lane >> 2;                         // value group 0..7

    for (int e = 0; e < cnt; e++) {
        const unsigned ent = bucket[e];              // warp-uniform, L1-warm
        const int b = (int)(ent >> 20);
        const unsigned i = ent & 0xFFFFFu;           // entry id = b*K1+k

        const size_t foff = (size_t)b * 32 + lane;
        const float4 fl = __ldg((const float4*)l   + foff);
        const float4 fa = __ldg((const float4*)ab  + foff);
        const float4 fo = __ldg((const float4*)ori + foff);

        float s0 = vl.x * fa.x + vl.y * fa.y + vl.z * fa.z + vl.w * fa.w;  // ab2l
        float s2 = vl.x * fo.x + vl.y * fo.y + vl.z * fo.z + vl.w * fo.w;  // ori2l
        float s1 = va.x * fl.x + va.y * fl.y + va.z * fl.z + va.w * fl.w;  // l2ab
        float s5 = va.x * fo.x + va.y * fo.y + va.z * fo.z + va.w * fo.w;  // ori2ab
        float s3 = vo.x * fl.x + vo.y * fl.y + vo.z * fl.z + vo.w * fl.w;  // l2ori
        float s4 = vo.x * fa.x + vo.y * fa.y + vo.z * fa.z + vo.w * fa.w;  // ab2ori

        // phase 1: 3 butterfly rounds -> equal (lane&3) hold class partials
        #pragma unroll
        for (int off = 16; off >= 4; off >>= 1) {
            s0 += __shfl_xor_sync(0xffffffffu, s0, off);
            s1 += __shfl_xor_sync(0xffffffffu, s1, off);
            s2 += __shfl_xor_sync(0xffffffffu, s2, off);
            s3 += __shfl_xor_sync(0xffffffffu, s3, off);
            s4 += __shfl_xor_sync(0xffffffffu, s4, off);
            s5 += __shfl_xor_sync(0xffffffffu, s5, off);
        }
        // phase 2: lane group v finishes value s_v
        float sel = (v == 0) ? s0 : (v == 1) ? s1 : (v == 2) ? s2
                  : (v == 3) ? s3 : (v == 4) ? s4 : s5;
        sel += __shfl_xor_sync(0xffffffffu, sel, 1);
        sel += __shfl_xor_sync(0xffffffffu, sel, 2);

        // lanes 0,4,8,12,16,20 write s0..s5 -> one 32B sector
        if (lane < 24 && (lane & 3) == 0)
            g_scores[(size_t)i * 8 + v] = sel;
    }
}

// ---------------------------------------------------------------------------
// 3) transpose staging -> plane-major output (staging L2-hit), 2 entries per
//    thread for ILP; momentum update of the 128 touched rows; re-zero g_cnt.
//    Stack order: [ab2l, l2ab, ori2l, l2ori, ab2ori, ori2ab]
// ---------------------------------------------------------------------------
__device__ __forceinline__ void transpose_one(float* __restrict__ outs, int i) {
    const float4 a = *((const float4*)(g_scores + (size_t)i * 8));
    const float4 c = *((const float4*)(g_scores + (size_t)i * 8) + 1);
    __stcs(&outs[0 * (size_t)SCORE_STRIDE + i], a.x);  // ab2l
    __stcs(&outs[1 * (size_t)SCORE_STRIDE + i], a.y);  // l2ab
    __stcs(&outs[2 * (size_t)SCORE_STRIDE + i], a.z);  // ori2l
    __stcs(&outs[3 * (size_t)SCORE_STRIDE + i], a.w);  // l2ori
    __stcs(&outs[4 * (size_t)SCORE_STRIDE + i], c.x);  // ab2ori
    __stcs(&outs[5 * (size_t)SCORE_STRIDE + i], c.y);  // ori2ab
}

__global__ __launch_bounds__(256) void final_kernel(
    float* __restrict__ outs,
    const float* __restrict__ l,
    const float* __restrict__ ab,
    const float* __restrict__ ori,
    const int* __restrict__ y,
    const float* __restrict__ ml,
    const float* __restrict__ mab,
    const float* __restrict__ mori,
    float* __restrict__ nl,
    float* __restrict__ nab,
    float* __restrict__ nori)
{
    const int bid = blockIdx.x;

    if (bid < FBLKS) {
        const int i0 = bid * 512 + threadIdx.x;      // two strided entries
        const int i1 = i0 + 256;
        if (i0 < NENTRIES) transpose_one(outs, i0);
        if (i1 < NENTRIES) transpose_one(outs, i1);
        return;
    }

    if (bid >= FBLKS + BATCH) {
        // re-zero g_cnt for the next kernel_launch call (after main read it)
        const int i = (bid - FBLKS - BATCH) * 256 + threadIdx.x;
        if (i < OUTPUT_SIZE / 4)
            reinterpret_cast<int4*>(g_cnt)[i] = make_int4(0, 0, 0, 0);
        return;
    }

    // ---- momentum update: one block per batch element ----
    __shared__ int sy[BATCH];
    __shared__ float red[12];

    const int b = bid - FBLKS;
    const int d = threadIdx.x;
    if (d < BATCH) sy[d] = y[d];
    __syncthreads();
    if (d >= BATCH) return;

    const int row = sy[b];
    for (int j = b + 1; j < BATCH; ++j)
        if (sy[j] == row) return;            // last occurrence wins

    const size_t mo = (size_t)row * DIM + d;
    const size_t fo = (size_t)b * DIM + d;

    const float pl = ml[mo]   * MOMENTUM + l[fo]   * (1.0f - MOMENTUM);
    const float pa = mab[mo]  * MOMENTUM + ab[fo]  * (1.0f - MOMENTUM);
    const float po = mori[mo] * MOMENTUM + ori[fo] * (1.0f - MOMENTUM);

    float vl = pl * pl, va = pa * pa, vo = po * po;
    #pragma unroll
    for (int off = 16; off > 0; off >>= 1) {
        vl += __shfl_xor_sync(0xffffffffu, vl, off);
        va += __shfl_xor_sync(0xffffffffu, va, off);
        vo += __shfl_xor_sync(0xffffffffu, vo, off);
    }
    const int w = d >> 5;
    if ((d & 31) == 0) { red[w] = vl; red[4 + w] = va; red[8 + w] = vo; }
    __syncthreads();

    const float suml = red[0] + red[1] + red[2]  + red[3];
    const float suma = red[4] + red[5] + red[6]  + red[7];
    const float sumo = red[8] + red[9] + red[10] + red[11];

    nl[mo]   = pl / sqrtf(suml);
    nab[mo]  = pa / sqrtf(suma);
    nori[mo] = po / sqrtf(sumo);
}

// ---------------------------------------------------------------------------
extern "C" void kernel_launch(void* const* d_in, const int* in_sizes, int n_in,
                              void* d_out, int out_size)
{
    const float* l    = (const float*)d_in[0];
    const float* ab   = (const float*)d_in[1];
    const float* ori  = (const float*)d_in[2];
    const int*   y    = (const int*)d_in[3];
    const int*   idx  = (const int*)d_in[4];
    const float* ml   = (const float*)d_in[5];
    const float* mab  = (const float*)d_in[6];
    const float* mori = (const float*)d_in[7];

    float* outs = (float*)d_out;
    float* nl   = outs + (size_t)6 * SCORE_STRIDE;
    float* nab  = nl  + (size_t)BANK_ELEMS;
    float* nori = nab + (size_t)BANK_ELEMS;

    scatter_kernel<<<(NENTRIES + 255) / 256, 256>>>(idx);
    main_kernel<<<OUTPUT_SIZE / 8, 256>>>(l, ab, ori, ml, mab, mori,
                                          nl, nab, nori);
    final_kernel<<<FBLKS + BATCH + ZBLKS, 256>>>(outs, l, ab, ori, y,
                                                 ml, mab, mori, nl, nab, nori);
}

// round 16
// speedup vs baseline: 1.0078x; 1.0078x over previous
#include <cuda_runtime.h>
#include <cuda_bf16.h>

#define BATCH 128
#define DIM 128
#define K1 4097                              // K + 1
#define OUTPUT_SIZE 200000
#define NENTRIES (BATCH * K1)                // 524416 (b,k) pairs
#define SCORE_STRIDE NENTRIES                // per score plane
#define BANK_ELEMS (OUTPUT_SIZE * DIM)       // 25,600,000 floats per bank
#define MOMENTUM 0.5f

// Fixed-slot inverted index. Entries per row ~ Poisson(2.62); P(count>16)
// summed over 200000 rows ~ 2e-4 for a uniform draw; observed max 13 here.
#define SLOTS 16

// __device__ globals are zero-initialized at module load; g_cnt is re-zeroed
// by main_kernel (each warp zeroes the row word it consumed), so the
// "g_cnt == 0 on entry" invariant holds for every call. The update flag is
// packed into bit 16 of the same word (atomicOr commutes with the counting
// atomicAdd in the low bits -> deterministic final word).
__device__ int      g_cnt[OUTPUT_SIZE];              // low 16: count, bit16: y-flag
__device__ unsigned g_entries[OUTPUT_SIZE * SLOTS];  // packed (b<<20)|i
__device__ float    g_scores[NENTRIES * 8];          // 6 sums, 32B/entry slot

#define SBLKS ((NENTRIES + 255) / 256)               // 2049 scatter blocks
#define FBLKS ((NENTRIES + 511) / 512)               // 1025 transpose blocks

// ---------------------------------------------------------------------------
// 1) scatter + momentum update in one launch.
//    Blocks [0, SBLKS): bucket every entry under its bank row (atomic bump).
//    Blocks [SBLKS, SBLKS+BATCH): momentum update of row y[b] (last batch
//    occurrence wins), writing the output banks directly and setting bit 16
//    of g_cnt[row] so main_kernel skips its copy-stores for that row.
//    These update blocks hide inside the scatter's latency (issue was 5%).
// ---------------------------------------------------------------------------
__global__ __launch_bounds__(256) void scatter_kernel(
    const int* __restrict__ idx,
    const int* __restrict__ y,
    const float* __restrict__ l,
    const float* __restrict__ ab,
    const float* __restrict__ ori,
    const float* __restrict__ ml,
    const float* __restrict__ mab,
    const float* __restrict__ mori,
    float* __restrict__ nl,
    float* __restrict__ nab,
    float* __restrict__ nori)
{
    const int bid = blockIdx.x;

    if (bid < SBLKS) {
        const int i = bid * 256 + threadIdx.x;
        if (i >= NENTRIES) return;
        const int r = __ldcs(&idx[i]);
        const int pos = atomicAdd(&g_cnt[r], 1) & 0xFFFF;
        const unsigned b = (unsigned)i / K1;         // one div here, not in main
        if (pos < SLOTS)
            g_entries[r * SLOTS + pos] = (b << 20) | (unsigned)i;
        return;
    }

    // ---- momentum update: one block per batch element ----
    __shared__ int sy[BATCH];
    __shared__ float red[12];

    const int b = bid - SBLKS;
    const int d = threadIdx.x;
    if (d < BATCH) sy[d] = y[d];
    __syncthreads();
    if (d >= BATCH) return;

    const int row = sy[b];
    for (int j = b + 1; j < BATCH; ++j)
        if (sy[j] == row) return;            // last occurrence wins

    const size_t mo = (size_t)row * DIM + d;
    const size_t fo = (size_t)b * DIM + d;

    const float pl = ml[mo]   * MOMENTUM + l[fo]   * (1.0f - MOMENTUM);
    const float pa = mab[mo]  * MOMENTUM + ab[fo]  * (1.0f - MOMENTUM);
    const float po = mori[mo] * MOMENTUM + ori[fo] * (1.0f - MOMENTUM);

    float vl = pl * pl, va = pa * pa, vo = po * po;
    #pragma unroll
    for (int off = 16; off > 0; off >>= 1) {
        vl += __shfl_xor_sync(0xffffffffu, vl, off);
        va += __shfl_xor_sync(0xffffffffu, va, off);
        vo += __shfl_xor_sync(0xffffffffu, vo, off);
    }
    const int w = d >> 5;
    if ((d & 31) == 0) { red[w] = vl; red[4 + w] = va; red[8 + w] = vo; }
    __syncthreads();

    const float suml = red[0] + red[1] + red[2]  + red[3];
    const float suma = red[4] + red[5] + red[6]  + red[7];
    const float sumo = red[8] + red[9] + red[10] + red[11];

    nl[mo]   = pl / sqrtf(suml);
    nab[mo]  = pa / sqrtf(suma);
    nori[mo] = po / sqrtf(sumo);

    if (d == 0) atomicOr(&g_cnt[row], 1 << 16);   // tell main: skip the copy
}

// ---------------------------------------------------------------------------
// 2) main sweep: one warp per bank row (empirically optimal shape).
//    - 3 streaming float4 row reads (row lives in registers)
//    - 3 streaming stores = the bank copy (skipped for y-updated rows)
//    - lane 0 re-zeroes g_cnt[row] after consuming it (next-call invariant)
//    - per referencing entry: 3 L1-hot feature loads, 6 dots, 20-SHFL
//      two-phase reduction, one 32B-sector staging write.
// ---------------------------------------------------------------------------
__global__ __launch_bounds__(256) void main_kernel(
    const float* __restrict__ l,
    const float* __restrict__ ab,
    const float* __restrict__ ori,
    const float* __restrict__ ml,
    const float* __restrict__ mab,
    const float* __restrict__ mori,
    float* __restrict__ nl,
    float* __restrict__ nab,
    float* __restrict__ nori)
{
    const int warp = threadIdx.x >> 5;
    const int lane = threadIdx.x & 31;
    const int row  = blockIdx.x * 8 + warp;          // 25000*8 = 200000 exact

    const unsigned* __restrict__ bucket = g_entries + row * SLOTS;
    asm volatile("prefetch.global.L1 [%0];" :: "l"(bucket));

    const size_t voff = (size_t)row * 32 + lane;

    const float4 vl = __ldcs((const float4*)ml   + voff);
    const float4 va = __ldcs((const float4*)mab  + voff);
    const float4 vo = __ldcs((const float4*)mori + voff);

    const unsigned cw = (unsigned)g_cnt[row];        // warp-uniform broadcast
    if (lane == 0 && cw != 0) g_cnt[row] = 0;        // reset for next call
    int cnt = (int)(cw & 0xFFFFu);
    cnt = (cnt < SLOTS) ? cnt : SLOTS;

    if (!(cw >> 16)) {                               // not a y-updated row
        __stcs((float4*)nl   + voff, vl);
        __stcs((float4*)nab  + voff, va);
        __stcs((float4*)nori + voff, vo);
    }

    const int v = lane >> 2;                         // value group 0..7

    for (int e = 0; e < cnt; e++) {
        const unsigned ent = bucket[e];              // warp-uniform, L1-warm
        const int b = (int)(ent >> 20);
        const unsigned i = ent & 0xFFFFFu;           // entry id = b*K1+k

        const size_t foff = (size_t)b * 32 + lane;
        const float4 fl = __ldg((const float4*)l   + foff);
        const float4 fa = __ldg((const float4*)ab  + foff);
        const float4 fo = __ldg((const float4*)ori + foff);

        float s0 = vl.x * fa.x + vl.y * fa.y + vl.z * fa.z + vl.w * fa.w;  // ab2l
        float s2 = vl.x * fo.x + vl.y * fo.y + vl.z * fo.z + vl.w * fo.w;  // ori2l
        float s1 = va.x * fl.x + va.y * fl.y + va.z * fl.z + va.w * fl.w;  // l2ab
        float s5 = va.x * fo.x + va.y * fo.y + va.z * fo.z + va.w * fo.w;  // ori2ab
        float s3 = vo.x * fl.x + vo.y * fl.y + vo.z * fl.z + vo.w * fl.w;  // l2ori
        float s4 = vo.x * fa.x + vo.y * fa.y + vo.z * fa.z + vo.w * fa.w;  // ab2ori

        // phase 1: 3 butterfly rounds -> equal (lane&3) hold class partials
        #pragma unroll
        for (int off = 16; off >= 4; off >>= 1) {
            s0 += __shfl_xor_sync(0xffffffffu, s0, off);
            s1 += __shfl_xor_sync(0xffffffffu, s1, off);
            s2 += __shfl_xor_sync(0xffffffffu, s2, off);
            s3 += __shfl_xor_sync(0xffffffffu, s3, off);
            s4 += __shfl_xor_sync(0xffffffffu, s4, off);
            s5 += __shfl_xor_sync(0xffffffffu, s5, off);
        }
        // phase 2: lane group v finishes value s_v
        float sel = (v == 0) ? s0 : (v == 1) ? s1 : (v == 2) ? s2
                  : (v == 3) ? s3 : (v == 4) ? s4 : s5;
        sel += __shfl_xor_sync(0xffffffffu, sel, 1);
        sel += __shfl_xor_sync(0xffffffffu, sel, 2);

        // lanes 0,4,8,12,16,20 write s0..s5 -> one 32B sector
        if (lane < 24 && (lane & 3) == 0)
            g_scores[(size_t)i * 8 + v] = sel;
    }
}

// ---------------------------------------------------------------------------
// 3) transpose staging -> plane-major output (staging L2-hit), 2 entries per
//    thread for ILP. Pure transpose now — update and zeroing moved out.
//    Stack order: [ab2l, l2ab, ori2l, l2ori, ab2ori, ori2ab]
// ---------------------------------------------------------------------------
__device__ __forceinline__ void transpose_one(float* __restrict__ outs, int i) {
    const float4 a = *((const float4*)(g_scores + (size_t)i * 8));
    const float4 c = *((const float4*)(g_scores + (size_t)i * 8) + 1);
    __stcs(&outs[0 * (size_t)SCORE_STRIDE + i], a.x);  // ab2l
    __stcs(&outs[1 * (size_t)SCORE_STRIDE + i], a.y);  // l2ab
    __stcs(&outs[2 * (size_t)SCORE_STRIDE + i], a.z);  // ori2l
    __stcs(&outs[3 * (size_t)SCORE_STRIDE + i], a.w);  // l2ori
    __stcs(&outs[4 * (size_t)SCORE_STRIDE + i], c.x);  // ab2ori
    __stcs(&outs[5 * (size_t)SCORE_STRIDE + i], c.y);  // ori2ab
}

__global__ __launch_bounds__(256) void final_kernel(float* __restrict__ outs)
{
    const int i0 = blockIdx.x * 512 + threadIdx.x;   // two strided entries
    const int i1 = i0 + 256;
    if (i0 < NENTRIES) transpose_one(outs, i0);
    if (i1 < NENTRIES) transpose_one(outs, i1);
}

// ---------------------------------------------------------------------------
extern "C" void kernel_launch(void* const* d_in, const int* in_sizes, int n_in,
                              void* d_out, int out_size)
{
    const float* l    = (const float*)d_in[0];
    const float* ab   = (const float*)d_in[1];
    const float* ori  = (const float*)d_in[2];
    const int*   y    = (const int*)d_in[3];
    const int*   idx  = (const int*)d_in[4];
    const float* ml   = (const float*)d_in[5];
    const float* mab  = (const float*)d_in[6];
    const float* mori = (const float*)d_in[7];

    float* outs = (float*)d_out;
    float* nl   = outs + (size_t)6 * SCORE_STRIDE;
    float* nab  = nl  + (size_t)BANK_ELEMS;
    float* nori = nab + (size_t)BANK_ELEMS;

    scatter_kernel<<<SBLKS + BATCH, 256>>>(idx, y, l, ab, ori,
                                           ml, mab, mori, nl, nab, nori);
    main_kernel<<<OUTPUT_SIZE / 8, 256>>>(l, ab, ori, ml, mab, mori,
                                          nl, nab, nori);
    final_kernel<<<FBLKS, 256>>>(outs);
}